// round 4
// baseline (speedup 1.0000x reference)
#include <cuda_runtime.h>

// z = max(-(x @ W^T + b), -1000)   x:[B,5] f32, W:[5,5], b:[5]
// Latency/occupancy-optimized: W,b in shared (frees ~30 regs), in-place
// row compute, streaming stores to keep x L2-resident across replays.
// (Resubmission of R2 kernel — previous bench died on container infra.)

#define NCOL 5
#define RPT  4   // rows per thread: 4 rows = 20 floats = 5 aligned float4

__global__ __launch_bounds__(256, 6) void qp_kernel(
    const float* __restrict__ x,
    const float* __restrict__ W,
    const float* __restrict__ b,
    float* __restrict__ out,
    int B)
{
    __shared__ float sw[25];
    __shared__ float sb[NCOL];
    if (threadIdx.x < 25) sw[threadIdx.x] = W[threadIdx.x];
    if (threadIdx.x < NCOL) sb[threadIdx.x] = b[threadIdx.x];
    __syncthreads();

    const long long t = (long long)blockIdx.x * blockDim.x + threadIdx.x;
    const long long row0 = t * RPT;
    if (row0 >= B) return;

    if (row0 + RPT <= B) {
        // 4 rows = 5 float4 loads, 16B-aligned (row0 % 4 == 0 -> offset % 80 == 0)
        const float4* __restrict__ xv =
            reinterpret_cast<const float4*>(x + row0 * NCOL);
        float f[RPT * NCOL];
        #pragma unroll
        for (int i = 0; i < 5; i++) {
            float4 v = xv[i];
            f[4 * i + 0] = v.x; f[4 * i + 1] = v.y;
            f[4 * i + 2] = v.z; f[4 * i + 3] = v.w;
        }

        // Row-by-row: 5 temps live, overwrite f[] in place
        #pragma unroll
        for (int r = 0; r < RPT; r++) {
            float h[NCOL];
            #pragma unroll
            for (int j = 0; j < NCOL; j++) h[j] = sb[j];
            #pragma unroll
            for (int k = 0; k < NCOL; k++) {
                const float xk = f[r * NCOL + k];
                #pragma unroll
                for (int j = 0; j < NCOL; j++)
                    h[j] = fmaf(xk, sw[j * NCOL + k], h[j]);
            }
            #pragma unroll
            for (int j = 0; j < NCOL; j++)
                f[r * NCOL + j] = fmaxf(-h[j], -1000.0f);
        }

        // Streaming (evict-first) stores: keep L2 for the input tensor
        float4* __restrict__ ov = reinterpret_cast<float4*>(out + row0 * NCOL);
        #pragma unroll
        for (int i = 0; i < 5; i++) {
            float4 v = make_float4(f[4 * i + 0], f[4 * i + 1],
                                   f[4 * i + 2], f[4 * i + 3]);
            __stcs(ov + i, v);
        }
    } else {
        // Scalar tail (not hit for B = 4194304)
        for (long long r = row0; r < B; r++) {
            #pragma unroll
            for (int j = 0; j < NCOL; j++) {
                float h = sb[j];
                #pragma unroll
                for (int k = 0; k < NCOL; k++)
                    h = fmaf(x[r * NCOL + k], sw[j * NCOL + k], h);
                out[r * NCOL + j] = fmaxf(-h, -1000.0f);
            }
        }
    }
}

extern "C" void kernel_launch(void* const* d_in, const int* in_sizes, int n_in,
                              void* d_out, int out_size)
{
    const float* x = (const float*)d_in[0];
    const float* W = (const float*)d_in[1];
    const float* b = (const float*)d_in[2];
    float* out = (float*)d_out;

    const int B = in_sizes[0] / NCOL;
    const long long nthreads = ((long long)B + RPT - 1) / RPT;
    const int block = 256;
    const int grid = (int)((nthreads + block - 1) / block);

    qp_kernel<<<grid, block>>>(x, W, b, out, B);
}

// round 9
// speedup vs baseline: 1.3875x; 1.3875x over previous
#include <cuda_runtime.h>

// z = max(-(x @ W^T + b), -1000)   x:[B,5] f32, W:[5,5], b:[5]
// R1 structure (W,b in registers — NOT shared; LDS competes with LDG in the
// L1tex pipe, proven regression in R4) + streaming stores (__stcs) so the
// 84MB output write stream doesn't evict the 84MB input from the 126MB L2.
// (Resubmission — R5 bench died on container infra before running.)

#define ROWS_PER_THREAD 4
#define NCOL 5

__global__ __launch_bounds__(256) void qp_kernel(
    const float* __restrict__ x,
    const float* __restrict__ W,
    const float* __restrict__ b,
    float* __restrict__ out,
    int B)
{
    const unsigned t = blockIdx.x * blockDim.x + threadIdx.x;
    const unsigned row0 = t * ROWS_PER_THREAD;           // B*5 < 2^31: 32-bit ok
    if (row0 >= (unsigned)B) return;

    // Tiny operands in registers (L1/L2 broadcast hits, hoisted by ptxas)
    float w[25];
    #pragma unroll
    for (int i = 0; i < 25; i++) w[i] = __ldg(W + i);
    float bb[NCOL];
    #pragma unroll
    for (int j = 0; j < NCOL; j++) bb[j] = __ldg(b + j);

    if (row0 + ROWS_PER_THREAD <= (unsigned)B) {
        // 4 rows = 20 floats = 5 float4, 16B-aligned (row0 % 4 == 0)
        const float4* __restrict__ xv =
            reinterpret_cast<const float4*>(x + (size_t)row0 * NCOL);
        float f[20];
        #pragma unroll
        for (int i = 0; i < 5; i++) {
            float4 v = xv[i];
            f[4 * i + 0] = v.x; f[4 * i + 1] = v.y;
            f[4 * i + 2] = v.z; f[4 * i + 3] = v.w;
        }

        float o[20];
        #pragma unroll
        for (int r = 0; r < ROWS_PER_THREAD; r++) {
            #pragma unroll
            for (int j = 0; j < NCOL; j++) {
                float h = bb[j];
                #pragma unroll
                for (int k = 0; k < NCOL; k++)
                    h = fmaf(f[r * NCOL + k], w[j * NCOL + k], h);
                o[r * NCOL + j] = fmaxf(-h, -1000.0f);
            }
        }

        // Streaming (evict-first) stores: keep L2 capacity for the input
        float4* __restrict__ ov =
            reinterpret_cast<float4*>(out + (size_t)row0 * NCOL);
        #pragma unroll
        for (int i = 0; i < 5; i++)
            __stcs(ov + i, make_float4(o[4 * i + 0], o[4 * i + 1],
                                       o[4 * i + 2], o[4 * i + 3]));
    } else {
        // Scalar tail (not hit for B = 4194304)
        for (unsigned r = row0; r < (unsigned)B; r++) {
            #pragma unroll
            for (int j = 0; j < NCOL; j++) {
                float h = bb[j];
                #pragma unroll
                for (int k = 0; k < NCOL; k++)
                    h = fmaf(x[(size_t)r * NCOL + k], w[j * NCOL + k], h);
                out[(size_t)r * NCOL + j] = fmaxf(-h, -1000.0f);
            }
        }
    }
}

extern "C" void kernel_launch(void* const* d_in, const int* in_sizes, int n_in,
                              void* d_out, int out_size)
{
    const float* x = (const float*)d_in[0];
    const float* W = (const float*)d_in[1];
    const float* b = (const float*)d_in[2];
    float* out = (float*)d_out;

    const int B = in_sizes[0] / NCOL;
    const long long nthreads =
        ((long long)B + ROWS_PER_THREAD - 1) / ROWS_PER_THREAD;
    const int block = 256;
    const int grid = (int)((nthreads + block - 1) / block);

    qp_kernel<<<grid, block>>>(x, W, b, out, B);
}